// round 5
// baseline (speedup 1.0000x reference)
#include <cuda_runtime.h>

#define N_NODES   100000
#define N_EDGES   800000
#define NF        64
#define NH        16
#define NG        64

// ---------------- scratch (static device globals; no allocation) ----------------
__device__ float g_y[N_NODES * NH];    // x @ W1_rel
__device__ float g_agg[N_NODES * NH];  // init: x @ W1_root + b1; then += segment_sum(y[src]) by dst
__device__ float g_t[N_NODES];         // relu(agg) . u
__device__ float g_u[NH];              // W2_rel @ Wlin
__device__ float g_w[NH];              // W2_root @ Wlin
__device__ float g_c;                  // b2 . Wlin
__device__ float g_S[NG];
__device__ float g_E[NG];
__device__ float g_cnt[NG];

// ---------------- K0: fold layer-2 weights into vectors; zero accumulators ------
__global__ void k0_setup(const float* __restrict__ W2_rel,
                         const float* __restrict__ W2_root,
                         const float* __restrict__ b2,
                         const float* __restrict__ Wlin) {
    int t = threadIdx.x;
    if (t < NH) {
        float u = 0.f, w = 0.f;
        #pragma unroll
        for (int j = 0; j < NH; ++j) {
            float lw = Wlin[j];
            u += W2_rel[t * NH + j]  * lw;
            w += W2_root[t * NH + j] * lw;
        }
        g_u[t] = u;
        g_w[t] = w;
    }
    if (t == 32) {
        float c = 0.f;
        #pragma unroll
        for (int j = 0; j < NH; ++j) c += b2[j] * Wlin[j];
        g_c = c;
    }
    if (t < NG) { g_S[t] = 0.f; g_E[t] = 0.f; g_cnt[t] = 0.f; }
}

// ---------------- K1: y = x @ W1_rel ; agg = x @ W1_root + b1 -------------------
// one thread per (node, h). 16 lanes share a node's x row (L1 broadcast),
// weight reads W[f*16+h] are coalesced across the 16 lanes.
__global__ void k1_node_proj(const float* __restrict__ x,
                             const float* __restrict__ W1_rel,
                             const float* __restrict__ W1_root,
                             const float* __restrict__ b1) {
    int i = blockIdx.x * blockDim.x + threadIdx.x;
    if (i >= N_NODES * NH) return;
    int n = i >> 4;
    int h = i & 15;
    const float4* xr = (const float4*)(x + (size_t)n * NF);
    float y = 0.f;
    float z = __ldg(b1 + h);
    #pragma unroll
    for (int f4 = 0; f4 < NF / 4; ++f4) {
        float4 xv = __ldg(xr + f4);
        int f = f4 * 4;
        y += xv.x * __ldg(W1_rel  + (f + 0) * NH + h);
        y += xv.y * __ldg(W1_rel  + (f + 1) * NH + h);
        y += xv.z * __ldg(W1_rel  + (f + 2) * NH + h);
        y += xv.w * __ldg(W1_rel  + (f + 3) * NH + h);
        z += xv.x * __ldg(W1_root + (f + 0) * NH + h);
        z += xv.y * __ldg(W1_root + (f + 1) * NH + h);
        z += xv.z * __ldg(W1_root + (f + 2) * NH + h);
        z += xv.w * __ldg(W1_root + (f + 3) * NH + h);
    }
    g_y[i]   = y;
    g_agg[i] = z;
}

// ---------------- K2: agg[dst] += y[src]  (4 lanes per edge, float4 gather) -----
__global__ void k2_edge_scatter(const int* __restrict__ edge_index) {
    long long i = (long long)blockIdx.x * blockDim.x + threadIdx.x;
    if (i >= (long long)N_EDGES * 4) return;
    int e = (int)(i >> 2);          // edge id
    int q = (int)(i & 3);           // which float4 of the 16-wide row
    int src = __ldg(edge_index + e);
    int dst = __ldg(edge_index + N_EDGES + e);
    float4 v = __ldg((const float4*)(g_y + (size_t)src * NH) + q);
    float* d = g_agg + (size_t)dst * NH + q * 4;
    atomicAdd(d + 0, v.x);
    atomicAdd(d + 1, v.y);
    atomicAdd(d + 2, v.z);
    atomicAdd(d + 3, v.w);
}

// ---------------- K3: h1 = relu(agg); per-node scalars; bin S, cnt by graph -----
__global__ void k3_node_scalars(const int* __restrict__ batch) {
    __shared__ float sS[NG];
    __shared__ float sC[NG];
    int t = threadIdx.x;
    if (t < NG) { sS[t] = 0.f; sC[t] = 0.f; }
    __syncthreads();

    int n = blockIdx.x * blockDim.x + t;
    if (n < N_NODES) {
        float s = 0.f, tv = 0.f;
        const float4* ar = (const float4*)(g_agg + (size_t)n * NH);
        #pragma unroll
        for (int q = 0; q < 4; ++q) {
            float4 a = ar[q];
            float v0 = fmaxf(a.x, 0.f);
            float v1 = fmaxf(a.y, 0.f);
            float v2 = fmaxf(a.z, 0.f);
            float v3 = fmaxf(a.w, 0.f);
            int h = q * 4;
            s  += v0 * g_w[h + 0] + v1 * g_w[h + 1] + v2 * g_w[h + 2] + v3 * g_w[h + 3];
            tv += v0 * g_u[h + 0] + v1 * g_u[h + 1] + v2 * g_u[h + 2] + v3 * g_u[h + 3];
        }
        s += g_c;
        g_t[n] = tv;
        int g = __ldg(batch + n);
        atomicAdd(&sS[g], s);
        atomicAdd(&sC[g], 1.f);
    }
    __syncthreads();
    if (t < NG) {
        if (sC[t] != 0.f) {
            atomicAdd(&g_S[t], sS[t]);
            atomicAdd(&g_cnt[t], sC[t]);
        }
    }
}

// ---------------- K4: E[batch[dst]] += t[src] ------------------------------------
__global__ void k4_edge_scalar(const int* __restrict__ edge_index,
                               const int* __restrict__ batch) {
    __shared__ float sE[NG];
    int t = threadIdx.x;
    if (t < NG) sE[t] = 0.f;
    __syncthreads();

    int e = blockIdx.x * blockDim.x + t;
    if (e < N_EDGES) {
        int src = __ldg(edge_index + e);
        int dst = __ldg(edge_index + N_EDGES + e);
        float tv = g_t[src];
        int g = __ldg(batch + dst);
        atomicAdd(&sE[g], tv);
    }
    __syncthreads();
    if (t < NG && sE[t] != 0.f) atomicAdd(&g_E[t], sE[t]);
}

// ---------------- K5: out[g] = (S+E)/max(cnt,1) + blin ---------------------------
__global__ void k5_final(const float* __restrict__ blin, float* __restrict__ out) {
    int g = threadIdx.x;
    if (g < NG) {
        float cnt = g_cnt[g];
        out[g] = (g_S[g] + g_E[g]) / fmaxf(cnt, 1.f) + blin[0];
    }
}

extern "C" void kernel_launch(void* const* d_in, const int* in_sizes, int n_in,
                              void* d_out, int out_size) {
    const float* x       = (const float*)d_in[0];
    const int*   eidx    = (const int*)d_in[1];    // int32 (JAX x64 disabled)
    const int*   batch   = (const int*)d_in[2];    // int32
    const float* W1_rel  = (const float*)d_in[3];
    const float* W1_root = (const float*)d_in[4];
    const float* b1      = (const float*)d_in[5];
    const float* W2_rel  = (const float*)d_in[6];
    const float* W2_root = (const float*)d_in[7];
    const float* b2      = (const float*)d_in[8];
    const float* Wlin    = (const float*)d_in[9];
    const float* blin    = (const float*)d_in[10];
    float* out = (float*)d_out;

    k0_setup<<<1, 128>>>(W2_rel, W2_root, b2, Wlin);

    {
        int total = N_NODES * NH;
        int tpb = 256;
        k1_node_proj<<<(total + tpb - 1) / tpb, tpb>>>(x, W1_rel, W1_root, b1);
    }
    {
        long long total = (long long)N_EDGES * 4;
        int tpb = 256;
        int blocks = (int)((total + tpb - 1) / tpb);
        k2_edge_scatter<<<blocks, tpb>>>(eidx);
    }
    {
        int tpb = 256;
        k3_node_scalars<<<(N_NODES + tpb - 1) / tpb, tpb>>>(batch);
    }
    {
        int tpb = 256;
        k4_edge_scalar<<<(N_EDGES + tpb - 1) / tpb, tpb>>>(eidx, batch);
    }
    k5_final<<<1, 64>>>(blin, out);
}

// round 8
// speedup vs baseline: 1.2427x; 1.2427x over previous
#include <cuda_runtime.h>

#define N_NODES   100000
#define N_EDGES   800000
#define NF        64
#define NH        16
#define NG        64
#define FULLMASK  0xFFFFFFFFu

// ---------------- scratch (static device globals; no allocation) ----------------
__device__ __align__(16) float g_y[N_NODES * NH];    // x @ W1_rel
__device__ __align__(16) float g_agg[N_NODES * NH];  // x @ W1_root + b1, += seg_sum(y[src]) by dst
__device__ float g_t[N_NODES];         // relu(agg) . u
__device__ __align__(16) float4 g_u4[NH / 4];        // W2_rel @ Wlin  (packed)
__device__ __align__(16) float4 g_w4[NH / 4];        // W2_root @ Wlin (packed)
__device__ float g_c;                  // b2 . Wlin
__device__ float g_S[NG];
__device__ float g_E[NG];
__device__ float g_cnt[NG];

// ---------------- K0: fold layer-2 weights into vectors; zero accumulators ------
__global__ void k0_setup(const float* __restrict__ W2_rel,
                         const float* __restrict__ W2_root,
                         const float* __restrict__ b2,
                         const float* __restrict__ Wlin) {
    int t = threadIdx.x;
    __shared__ float su[NH], sw[NH];
    if (t < NH) {
        float u = 0.f, w = 0.f;
        #pragma unroll
        for (int j = 0; j < NH; ++j) {
            float lw = Wlin[j];
            u += W2_rel[t * NH + j]  * lw;
            w += W2_root[t * NH + j] * lw;
        }
        su[t] = u;
        sw[t] = w;
    }
    if (t == 32) {
        float c = 0.f;
        #pragma unroll
        for (int j = 0; j < NH; ++j) c += b2[j] * Wlin[j];
        g_c = c;
    }
    if (t < NG) { g_S[t] = 0.f; g_E[t] = 0.f; g_cnt[t] = 0.f; }
    __syncthreads();
    if (t < NH / 4) {
        g_u4[t] = make_float4(su[t*4], su[t*4+1], su[t*4+2], su[t*4+3]);
        g_w4[t] = make_float4(sw[t*4], sw[t*4+1], sw[t*4+2], sw[t*4+3]);
    }
}

// ---------------- K1: y = x @ W1_rel ; agg = x @ W1_root + b1 -------------------
__global__ void k1_node_proj(const float* __restrict__ x,
                             const float* __restrict__ W1_rel,
                             const float* __restrict__ W1_root,
                             const float* __restrict__ b1) {
    int i = blockIdx.x * blockDim.x + threadIdx.x;
    if (i >= N_NODES * NH) return;
    int n = i >> 4;
    int h = i & 15;
    const float4* xr = (const float4*)(x + (size_t)n * NF);
    float y = 0.f;
    float z = __ldg(b1 + h);
    #pragma unroll
    for (int f4 = 0; f4 < NF / 4; ++f4) {
        float4 xv = __ldg(xr + f4);
        int f = f4 * 4;
        y += xv.x * __ldg(W1_rel  + (f + 0) * NH + h);
        y += xv.y * __ldg(W1_rel  + (f + 1) * NH + h);
        y += xv.z * __ldg(W1_rel  + (f + 2) * NH + h);
        y += xv.w * __ldg(W1_rel  + (f + 3) * NH + h);
        z += xv.x * __ldg(W1_root + (f + 0) * NH + h);
        z += xv.y * __ldg(W1_root + (f + 1) * NH + h);
        z += xv.z * __ldg(W1_root + (f + 2) * NH + h);
        z += xv.w * __ldg(W1_root + (f + 3) * NH + h);
    }
    g_y[i]   = y;
    g_agg[i] = z;
}

// ---------------- K2: agg[dst] += y[src]  (4 lanes/edge, one v4 RED per lane) ---
__global__ void k2_edge_scatter(const int* __restrict__ edge_index) {
    long long i = (long long)blockIdx.x * blockDim.x + threadIdx.x;
    if (i >= (long long)N_EDGES * 4) return;
    int e = (int)(i >> 2);          // edge id
    int q = (int)(i & 3);           // which float4 of the 16-wide row
    int src = __ldg(edge_index + e);
    int dst = __ldg(edge_index + N_EDGES + e);
    float4 v = __ldg((const float4*)(g_y + (size_t)src * NH) + q);
    float* d = g_agg + (size_t)dst * NH + q * 4;
    unsigned long long gaddr = (unsigned long long)__cvta_generic_to_global(d);
    asm volatile("red.global.add.v4.f32 [%0], {%1, %2, %3, %4};"
                 :: "l"(gaddr), "f"(v.x), "f"(v.y), "f"(v.z), "f"(v.w)
                 : "memory");
}

// ---------------- K3: h1 = relu(agg); per-node scalars; warp-binned pooling -----
// 4 lanes per node; 8 nodes per warp. batch is sorted -> warp almost always
// covers a single graph: full-warp reduce + 2 global REDs per warp.
__global__ void k3_node_scalars(const int* __restrict__ batch) {
    int lane = threadIdx.x & 31;
    int q = lane & 3;
    int warp_id = (blockIdx.x * blockDim.x + threadIdx.x) >> 5;
    int node = warp_id * 8 + (lane >> 2);
    bool valid = node < N_NODES;

    float4 a = make_float4(0.f, 0.f, 0.f, 0.f);
    int g = 0;
    if (valid) {
        a = __ldg((const float4*)(g_agg + (size_t)node * NH) + q);
        g = __ldg(batch + node);
    }
    float v0 = fmaxf(a.x, 0.f), v1 = fmaxf(a.y, 0.f);
    float v2 = fmaxf(a.z, 0.f), v3 = fmaxf(a.w, 0.f);
    float4 wq = g_w4[q];
    float4 uq = g_u4[q];
    float s  = v0 * wq.x + v1 * wq.y + v2 * wq.z + v3 * wq.w;
    float tv = v0 * uq.x + v1 * uq.y + v2 * uq.z + v3 * uq.w;

    // reduce over the 4 lanes of this node
    s  += __shfl_xor_sync(FULLMASK, s, 1);
    s  += __shfl_xor_sync(FULLMASK, s, 2);
    tv += __shfl_xor_sync(FULLMASK, tv, 1);
    tv += __shfl_xor_sync(FULLMASK, tv, 2);
    if (valid && q == 0) g_t[node] = tv;

    unsigned ballot_valid = __ballot_sync(FULLMASK, valid && q == 0);
    if (ballot_valid == 0) return;
    int nv = __popc(ballot_valid);

    int g0 = __shfl_sync(FULLMASK, g, 0);   // lane 0 is valid if any lane is
    bool uniform = __all_sync(FULLMASK, (g == g0) || !valid);

    if (uniform) {
        // sum s over the 8 nodes (lanes within a group hold identical s)
        float ss = s;
        ss += __shfl_xor_sync(FULLMASK, ss, 4);
        ss += __shfl_xor_sync(FULLMASK, ss, 8);
        ss += __shfl_xor_sync(FULLMASK, ss, 16);
        if (lane == 0) {
            atomicAdd(&g_S[g0], ss + g_c * (float)nv);
            atomicAdd(&g_cnt[g0], (float)nv);
        }
    } else {
        if (valid && q == 0) {
            atomicAdd(&g_S[g], s + g_c);
            atomicAdd(&g_cnt[g], 1.f);
        }
    }
}

// ---------------- K4: E[batch[dst]] += t[src] ------------------------------------
__global__ void k4_edge_scalar(const int* __restrict__ edge_index,
                               const int* __restrict__ batch) {
    __shared__ float sE[NG];
    int t = threadIdx.x;
    if (t < NG) sE[t] = 0.f;
    __syncthreads();

    int e = blockIdx.x * blockDim.x + t;
    if (e < N_EDGES) {
        int src = __ldg(edge_index + e);
        int dst = __ldg(edge_index + N_EDGES + e);
        float tv = g_t[src];
        int g = __ldg(batch + dst);
        atomicAdd(&sE[g], tv);
    }
    __syncthreads();
    if (t < NG && sE[t] != 0.f) atomicAdd(&g_E[t], sE[t]);
}

// ---------------- K5: out[g] = (S+E)/max(cnt,1) + blin ---------------------------
__global__ void k5_final(const float* __restrict__ blin, float* __restrict__ out) {
    int g = threadIdx.x;
    if (g < NG) {
        float cnt = g_cnt[g];
        out[g] = (g_S[g] + g_E[g]) / fmaxf(cnt, 1.f) + blin[0];
    }
}

extern "C" void kernel_launch(void* const* d_in, const int* in_sizes, int n_in,
                              void* d_out, int out_size) {
    const float* x       = (const float*)d_in[0];
    const int*   eidx    = (const int*)d_in[1];    // int32 (JAX x64 disabled)
    const int*   batch   = (const int*)d_in[2];    // int32
    const float* W1_rel  = (const float*)d_in[3];
    const float* W1_root = (const float*)d_in[4];
    const float* b1      = (const float*)d_in[5];
    const float* W2_rel  = (const float*)d_in[6];
    const float* W2_root = (const float*)d_in[7];
    const float* b2      = (const float*)d_in[8];
    const float* Wlin    = (const float*)d_in[9];
    const float* blin    = (const float*)d_in[10];
    float* out = (float*)d_out;

    k0_setup<<<1, 128>>>(W2_rel, W2_root, b2, Wlin);

    {
        int total = N_NODES * NH;
        int tpb = 256;
        k1_node_proj<<<(total + tpb - 1) / tpb, tpb>>>(x, W1_rel, W1_root, b1);
    }
    {
        long long total = (long long)N_EDGES * 4;
        int tpb = 256;
        int blocks = (int)((total + tpb - 1) / tpb);
        k2_edge_scatter<<<blocks, tpb>>>(eidx);
    }
    {
        int total = ((N_NODES + 7) / 8) * 32;  // 4 lanes per node
        int tpb = 256;
        k3_node_scalars<<<(total + tpb - 1) / tpb, tpb>>>(batch);
    }
    {
        int tpb = 256;
        k4_edge_scalar<<<(N_EDGES + tpb - 1) / tpb, tpb>>>(eidx, batch);
    }
    k5_final<<<1, 64>>>(blin, out);
}

// round 11
// speedup vs baseline: 1.3381x; 1.0768x over previous
#include <cuda_runtime.h>

#define N_NODES   100000
#define N_EDGES   800000
#define NF        64
#define NH        16
#define NG        64
#define FULLMASK  0xFFFFFFFFu

// ---------------- scratch (static device globals; no allocation) ----------------
__device__ __align__(16) float g_y[N_NODES * NH];    // x @ W1_rel
__device__ __align__(16) float g_agg[N_NODES * NH];  // x @ W1_root + b1, += seg_sum(y[src]) by dst
__device__ float g_t[N_NODES];         // relu(agg) . u
__device__ __align__(16) float4 g_u4[NH / 4];        // W2_rel @ Wlin  (packed)
__device__ __align__(16) float4 g_w4[NH / 4];        // W2_root @ Wlin (packed)
__device__ float g_c;                  // b2 . Wlin
__device__ float g_S[NG];
__device__ float g_E[NG];
__device__ float g_cnt[NG];

// ---------------- K0: fold layer-2 weights into vectors; zero accumulators ------
__global__ void k0_setup(const float* __restrict__ W2_rel,
                         const float* __restrict__ W2_root,
                         const float* __restrict__ b2,
                         const float* __restrict__ Wlin) {
    int t = threadIdx.x;
    __shared__ float su[NH], sw[NH];
    if (t < NH) {
        float u = 0.f, w = 0.f;
        #pragma unroll
        for (int j = 0; j < NH; ++j) {
            float lw = Wlin[j];
            u += W2_rel[t * NH + j]  * lw;
            w += W2_root[t * NH + j] * lw;
        }
        su[t] = u;
        sw[t] = w;
    }
    if (t == 32) {
        float c = 0.f;
        #pragma unroll
        for (int j = 0; j < NH; ++j) c += b2[j] * Wlin[j];
        g_c = c;
    }
    if (t < NG) { g_S[t] = 0.f; g_E[t] = 0.f; g_cnt[t] = 0.f; }
    __syncthreads();
    if (t < NH / 4) {
        g_u4[t] = make_float4(su[t*4], su[t*4+1], su[t*4+2], su[t*4+3]);
        g_w4[t] = make_float4(sw[t*4], sw[t*4+1], sw[t*4+2], sw[t*4+3]);
    }
}

// ---------------- K1: y = x @ W1_rel ; agg = x @ W1_root + b1 -------------------
__global__ void k1_node_proj(const float* __restrict__ x,
                             const float* __restrict__ W1_rel,
                             const float* __restrict__ W1_root,
                             const float* __restrict__ b1) {
    int i = blockIdx.x * blockDim.x + threadIdx.x;
    if (i >= N_NODES * NH) return;
    int n = i >> 4;
    int h = i & 15;
    const float4* xr = (const float4*)(x + (size_t)n * NF);
    float y = 0.f;
    float z = __ldg(b1 + h);
    #pragma unroll
    for (int f4 = 0; f4 < NF / 4; ++f4) {
        float4 xv = __ldg(xr + f4);
        int f = f4 * 4;
        y += xv.x * __ldg(W1_rel  + (f + 0) * NH + h);
        y += xv.y * __ldg(W1_rel  + (f + 1) * NH + h);
        y += xv.z * __ldg(W1_rel  + (f + 2) * NH + h);
        y += xv.w * __ldg(W1_rel  + (f + 3) * NH + h);
        z += xv.x * __ldg(W1_root + (f + 0) * NH + h);
        z += xv.y * __ldg(W1_root + (f + 1) * NH + h);
        z += xv.z * __ldg(W1_root + (f + 2) * NH + h);
        z += xv.w * __ldg(W1_root + (f + 3) * NH + h);
    }
    g_y[i]   = y;
    g_agg[i] = z;
}

// ---------------- K2: agg[dst] += y[src]  (1 thread/edge, MLP=4 both ways) ------
__global__ void k2_edge_scatter(const int* __restrict__ edge_index) {
    int e = blockIdx.x * blockDim.x + threadIdx.x;
    if (e >= N_EDGES) return;
    int src = __ldg(edge_index + e);
    int dst = __ldg(edge_index + N_EDGES + e);
    const float4* yr = (const float4*)(g_y + ((unsigned)src << 4));
    float4 v0 = __ldg(yr + 0);
    float4 v1 = __ldg(yr + 1);
    float4 v2 = __ldg(yr + 2);
    float4 v3 = __ldg(yr + 3);
    unsigned long long d =
        (unsigned long long)__cvta_generic_to_global(g_agg + ((unsigned)dst << 4));
    asm volatile("red.global.add.v4.f32 [%0], {%1, %2, %3, %4};"
                 :: "l"(d), "f"(v0.x), "f"(v0.y), "f"(v0.z), "f"(v0.w) : "memory");
    asm volatile("red.global.add.v4.f32 [%0], {%1, %2, %3, %4};"
                 :: "l"(d + 16), "f"(v1.x), "f"(v1.y), "f"(v1.z), "f"(v1.w) : "memory");
    asm volatile("red.global.add.v4.f32 [%0], {%1, %2, %3, %4};"
                 :: "l"(d + 32), "f"(v2.x), "f"(v2.y), "f"(v2.z), "f"(v2.w) : "memory");
    asm volatile("red.global.add.v4.f32 [%0], {%1, %2, %3, %4};"
                 :: "l"(d + 48), "f"(v3.x), "f"(v3.y), "f"(v3.z), "f"(v3.w) : "memory");
}

// ---------------- K3: h1 = relu(agg); per-node scalars; warp-binned pooling -----
// 1 thread per node, 4 independent float4 loads (MLP=4). batch sorted ->
// warp of 32 consecutive nodes is usually one graph: warp-reduce + 1 RED pair.
__global__ void k3_node_scalars(const int* __restrict__ batch) {
    int node = blockIdx.x * blockDim.x + threadIdx.x;
    bool valid = node < N_NODES;

    float4 a0, a1, a2, a3;
    int g = 0;
    if (valid) {
        const float4* ar = (const float4*)(g_agg + ((unsigned)node << 4));
        a0 = __ldg(ar + 0);
        a1 = __ldg(ar + 1);
        a2 = __ldg(ar + 2);
        a3 = __ldg(ar + 3);
        g = __ldg(batch + node);
    } else {
        a0 = a1 = a2 = a3 = make_float4(0.f, 0.f, 0.f, 0.f);
    }

    float4 w0 = g_w4[0], w1 = g_w4[1], w2 = g_w4[2], w3 = g_w4[3];
    float4 u0 = g_u4[0], u1 = g_u4[1], u2 = g_u4[2], u3 = g_u4[3];

    float s = 0.f, tv = 0.f;
    {
        float v;
        v = fmaxf(a0.x, 0.f); s += v * w0.x; tv += v * u0.x;
        v = fmaxf(a0.y, 0.f); s += v * w0.y; tv += v * u0.y;
        v = fmaxf(a0.z, 0.f); s += v * w0.z; tv += v * u0.z;
        v = fmaxf(a0.w, 0.f); s += v * w0.w; tv += v * u0.w;
        v = fmaxf(a1.x, 0.f); s += v * w1.x; tv += v * u1.x;
        v = fmaxf(a1.y, 0.f); s += v * w1.y; tv += v * u1.y;
        v = fmaxf(a1.z, 0.f); s += v * w1.z; tv += v * u1.z;
        v = fmaxf(a1.w, 0.f); s += v * w1.w; tv += v * u1.w;
        v = fmaxf(a2.x, 0.f); s += v * w2.x; tv += v * u2.x;
        v = fmaxf(a2.y, 0.f); s += v * w2.y; tv += v * u2.y;
        v = fmaxf(a2.z, 0.f); s += v * w2.z; tv += v * u2.z;
        v = fmaxf(a2.w, 0.f); s += v * w2.w; tv += v * u2.w;
        v = fmaxf(a3.x, 0.f); s += v * w3.x; tv += v * u3.x;
        v = fmaxf(a3.y, 0.f); s += v * w3.y; tv += v * u3.y;
        v = fmaxf(a3.z, 0.f); s += v * w3.z; tv += v * u3.z;
        v = fmaxf(a3.w, 0.f); s += v * w3.w; tv += v * u3.w;
    }
    if (valid) g_t[node] = tv;

    int lane = threadIdx.x & 31;
    unsigned ballot_valid = __ballot_sync(FULLMASK, valid);
    if (ballot_valid == 0) return;
    int nv = __popc(ballot_valid);

    int g0 = __shfl_sync(FULLMASK, g, 0);
    bool uniform = __all_sync(FULLMASK, (g == g0) || !valid);

    if (uniform) {
        float ss = valid ? s : 0.f;
        ss += __shfl_xor_sync(FULLMASK, ss, 1);
        ss += __shfl_xor_sync(FULLMASK, ss, 2);
        ss += __shfl_xor_sync(FULLMASK, ss, 4);
        ss += __shfl_xor_sync(FULLMASK, ss, 8);
        ss += __shfl_xor_sync(FULLMASK, ss, 16);
        if (lane == 0) {
            atomicAdd(&g_S[g0], ss + g_c * (float)nv);
            atomicAdd(&g_cnt[g0], (float)nv);
        }
    } else {
        if (valid) {
            atomicAdd(&g_S[g], s + g_c);
            atomicAdd(&g_cnt[g], 1.f);
        }
    }
}

// ---------------- K4: E[batch[dst]] += t[src]  (4 edges/thread, MLP=4) ----------
#define K4_EPT 4
__global__ void k4_edge_scalar(const int* __restrict__ edge_index,
                               const int* __restrict__ batch) {
    __shared__ float sE[NG];
    int t = threadIdx.x;
    if (t < NG) sE[t] = 0.f;
    __syncthreads();

    int base = blockIdx.x * blockDim.x * K4_EPT + t;
    int e0 = base;
    int e1 = base + blockDim.x;
    int e2 = base + blockDim.x * 2;
    int e3 = base + blockDim.x * 3;

    int s0 = 0, s1 = 0, s2 = 0, s3 = 0;
    int d0 = 0, d1 = 0, d2 = 0, d3 = 0;
    bool b0 = e0 < N_EDGES, b1 = e1 < N_EDGES, b2 = e2 < N_EDGES, b3 = e3 < N_EDGES;
    if (b0) { s0 = __ldg(edge_index + e0); d0 = __ldg(edge_index + N_EDGES + e0); }
    if (b1) { s1 = __ldg(edge_index + e1); d1 = __ldg(edge_index + N_EDGES + e1); }
    if (b2) { s2 = __ldg(edge_index + e2); d2 = __ldg(edge_index + N_EDGES + e2); }
    if (b3) { s3 = __ldg(edge_index + e3); d3 = __ldg(edge_index + N_EDGES + e3); }

    float t0 = 0.f, t1 = 0.f, t2 = 0.f, t3 = 0.f;
    int   gg0 = 0, gg1 = 0, gg2 = 0, gg3 = 0;
    if (b0) { t0 = __ldg(g_t + s0); gg0 = __ldg(batch + d0); }
    if (b1) { t1 = __ldg(g_t + s1); gg1 = __ldg(batch + d1); }
    if (b2) { t2 = __ldg(g_t + s2); gg2 = __ldg(batch + d2); }
    if (b3) { t3 = __ldg(g_t + s3); gg3 = __ldg(batch + d3); }

    if (b0) atomicAdd(&sE[gg0], t0);
    if (b1) atomicAdd(&sE[gg1], t1);
    if (b2) atomicAdd(&sE[gg2], t2);
    if (b3) atomicAdd(&sE[gg3], t3);

    __syncthreads();
    if (t < NG && sE[t] != 0.f) atomicAdd(&g_E[t], sE[t]);
}

// ---------------- K5: out[g] = (S+E)/max(cnt,1) + blin ---------------------------
__global__ void k5_final(const float* __restrict__ blin, float* __restrict__ out) {
    int g = threadIdx.x;
    if (g < NG) {
        float cnt = g_cnt[g];
        out[g] = (g_S[g] + g_E[g]) / fmaxf(cnt, 1.f) + blin[0];
    }
}

extern "C" void kernel_launch(void* const* d_in, const int* in_sizes, int n_in,
                              void* d_out, int out_size) {
    const float* x       = (const float*)d_in[0];
    const int*   eidx    = (const int*)d_in[1];    // int32 (JAX x64 disabled)
    const int*   batch   = (const int*)d_in[2];    // int32
    const float* W1_rel  = (const float*)d_in[3];
    const float* W1_root = (const float*)d_in[4];
    const float* b1      = (const float*)d_in[5];
    const float* W2_rel  = (const float*)d_in[6];
    const float* W2_root = (const float*)d_in[7];
    const float* b2      = (const float*)d_in[8];
    const float* Wlin    = (const float*)d_in[9];
    const float* blin    = (const float*)d_in[10];
    float* out = (float*)d_out;

    k0_setup<<<1, 128>>>(W2_rel, W2_root, b2, Wlin);

    {
        int total = N_NODES * NH;
        int tpb = 256;
        k1_node_proj<<<(total + tpb - 1) / tpb, tpb>>>(x, W1_rel, W1_root, b1);
    }
    {
        int tpb = 256;
        k2_edge_scatter<<<(N_EDGES + tpb - 1) / tpb, tpb>>>(eidx);
    }
    {
        int tpb = 128;
        k3_node_scalars<<<(N_NODES + tpb - 1) / tpb, tpb>>>(batch);
    }
    {
        int tpb = 256;
        int per_block = tpb * K4_EPT;
        k4_edge_scalar<<<(N_EDGES + per_block - 1) / per_block, tpb>>>(eidx, batch);
    }
    k5_final<<<1, 64>>>(blin, out);
}

// round 12
// speedup vs baseline: 1.3605x; 1.0167x over previous
#include <cuda_runtime.h>

#define N_NODES   100000
#define N_EDGES   800000
#define NF        64
#define NH        16
#define NG        64
#define FULLMASK  0xFFFFFFFFu

// ---------------- scratch (static device globals; no allocation) ----------------
__device__ __align__(16) float g_y[N_NODES * NH];    // x @ W1_rel
__device__ __align__(16) float g_agg[N_NODES * NH];  // x @ W1_root + b1, += seg_sum(y[src]) by dst
__device__ float g_t[N_NODES];         // relu(agg) . u
__device__ __align__(16) float4 g_u4[NH / 4];        // W2_rel @ Wlin  (packed)
__device__ __align__(16) float4 g_w4[NH / 4];        // W2_root @ Wlin (packed)
__device__ float g_c;                  // b2 . Wlin
__device__ float g_S[NG];
__device__ float g_E[NG];
__device__ float g_cnt[NG];

// ---------------- K0: fold layer-2 weights into vectors; zero accumulators ------
__global__ void k0_setup(const float* __restrict__ W2_rel,
                         const float* __restrict__ W2_root,
                         const float* __restrict__ b2,
                         const float* __restrict__ Wlin) {
    int t = threadIdx.x;
    __shared__ float su[NH], sw[NH];
    if (t < NH) {
        float u = 0.f, w = 0.f;
        #pragma unroll
        for (int j = 0; j < NH; ++j) {
            float lw = Wlin[j];
            u += W2_rel[t * NH + j]  * lw;
            w += W2_root[t * NH + j] * lw;
        }
        su[t] = u;
        sw[t] = w;
    }
    if (t == 32) {
        float c = 0.f;
        #pragma unroll
        for (int j = 0; j < NH; ++j) c += b2[j] * Wlin[j];
        g_c = c;
    }
    if (t < NG) { g_S[t] = 0.f; g_E[t] = 0.f; g_cnt[t] = 0.f; }
    __syncthreads();
    if (t < NH / 4) {
        g_u4[t] = make_float4(su[t*4], su[t*4+1], su[t*4+2], su[t*4+3]);
        g_w4[t] = make_float4(sw[t*4], sw[t*4+1], sw[t*4+2], sw[t*4+3]);
    }
}

// ---------------- K1: y = x @ W1_rel ; agg = x @ W1_root + b1 -------------------
__global__ void k1_node_proj(const float* __restrict__ x,
                             const float* __restrict__ W1_rel,
                             const float* __restrict__ W1_root,
                             const float* __restrict__ b1) {
    int i = blockIdx.x * blockDim.x + threadIdx.x;
    if (i >= N_NODES * NH) return;
    int n = i >> 4;
    int h = i & 15;
    const float4* xr = (const float4*)(x + (size_t)n * NF);
    float y = 0.f;
    float z = __ldg(b1 + h);
    #pragma unroll
    for (int f4 = 0; f4 < NF / 4; ++f4) {
        float4 xv = __ldg(xr + f4);
        int f = f4 * 4;
        y += xv.x * __ldg(W1_rel  + (f + 0) * NH + h);
        y += xv.y * __ldg(W1_rel  + (f + 1) * NH + h);
        y += xv.z * __ldg(W1_rel  + (f + 2) * NH + h);
        y += xv.w * __ldg(W1_rel  + (f + 3) * NH + h);
        z += xv.x * __ldg(W1_root + (f + 0) * NH + h);
        z += xv.y * __ldg(W1_root + (f + 1) * NH + h);
        z += xv.z * __ldg(W1_root + (f + 2) * NH + h);
        z += xv.w * __ldg(W1_root + (f + 3) * NH + h);
    }
    g_y[i]   = y;
    g_agg[i] = z;
}

// ---------------- K2: agg[dst] += y[src]  (1 thread/edge, MLP=4 both ways) ------
__global__ void k2_edge_scatter(const int* __restrict__ edge_index) {
    int e = blockIdx.x * blockDim.x + threadIdx.x;
    if (e >= N_EDGES) return;
    int src = __ldg(edge_index + e);
    int dst = __ldg(edge_index + N_EDGES + e);
    const float4* yr = (const float4*)(g_y + ((unsigned)src << 4));
    float4 v0 = __ldg(yr + 0);
    float4 v1 = __ldg(yr + 1);
    float4 v2 = __ldg(yr + 2);
    float4 v3 = __ldg(yr + 3);
    unsigned long long d =
        (unsigned long long)__cvta_generic_to_global(g_agg + ((unsigned)dst << 4));
    asm volatile("red.global.add.v4.f32 [%0], {%1, %2, %3, %4};"
                 :: "l"(d), "f"(v0.x), "f"(v0.y), "f"(v0.z), "f"(v0.w) : "memory");
    asm volatile("red.global.add.v4.f32 [%0], {%1, %2, %3, %4};"
                 :: "l"(d + 16), "f"(v1.x), "f"(v1.y), "f"(v1.z), "f"(v1.w) : "memory");
    asm volatile("red.global.add.v4.f32 [%0], {%1, %2, %3, %4};"
                 :: "l"(d + 32), "f"(v2.x), "f"(v2.y), "f"(v2.z), "f"(v2.w) : "memory");
    asm volatile("red.global.add.v4.f32 [%0], {%1, %2, %3, %4};"
                 :: "l"(d + 48), "f"(v3.x), "f"(v3.y), "f"(v3.z), "f"(v3.w) : "memory");
}

// ---------------- K3: h1 = relu(agg); per-node scalars; warp-binned pooling -----
// 1 thread per node, 4 independent float4 loads (MLP=4). batch sorted ->
// warp of 32 consecutive nodes is usually one graph: warp-reduce + 1 RED pair.
__global__ void k3_node_scalars(const int* __restrict__ batch) {
    int node = blockIdx.x * blockDim.x + threadIdx.x;
    bool valid = node < N_NODES;

    float4 a0, a1, a2, a3;
    int g = 0;
    if (valid) {
        const float4* ar = (const float4*)(g_agg + ((unsigned)node << 4));
        a0 = __ldg(ar + 0);
        a1 = __ldg(ar + 1);
        a2 = __ldg(ar + 2);
        a3 = __ldg(ar + 3);
        g = __ldg(batch + node);
    } else {
        a0 = a1 = a2 = a3 = make_float4(0.f, 0.f, 0.f, 0.f);
    }

    float4 w0 = g_w4[0], w1 = g_w4[1], w2 = g_w4[2], w3 = g_w4[3];
    float4 u0 = g_u4[0], u1 = g_u4[1], u2 = g_u4[2], u3 = g_u4[3];

    float s = 0.f, tv = 0.f;
    {
        float v;
        v = fmaxf(a0.x, 0.f); s += v * w0.x; tv += v * u0.x;
        v = fmaxf(a0.y, 0.f); s += v * w0.y; tv += v * u0.y;
        v = fmaxf(a0.z, 0.f); s += v * w0.z; tv += v * u0.z;
        v = fmaxf(a0.w, 0.f); s += v * w0.w; tv += v * u0.w;
        v = fmaxf(a1.x, 0.f); s += v * w1.x; tv += v * u1.x;
        v = fmaxf(a1.y, 0.f); s += v * w1.y; tv += v * u1.y;
        v = fmaxf(a1.z, 0.f); s += v * w1.z; tv += v * u1.z;
        v = fmaxf(a1.w, 0.f); s += v * w1.w; tv += v * u1.w;
        v = fmaxf(a2.x, 0.f); s += v * w2.x; tv += v * u2.x;
        v = fmaxf(a2.y, 0.f); s += v * w2.y; tv += v * u2.y;
        v = fmaxf(a2.z, 0.f); s += v * w2.z; tv += v * u2.z;
        v = fmaxf(a2.w, 0.f); s += v * w2.w; tv += v * u2.w;
        v = fmaxf(a3.x, 0.f); s += v * w3.x; tv += v * u3.x;
        v = fmaxf(a3.y, 0.f); s += v * w3.y; tv += v * u3.y;
        v = fmaxf(a3.z, 0.f); s += v * w3.z; tv += v * u3.z;
        v = fmaxf(a3.w, 0.f); s += v * w3.w; tv += v * u3.w;
    }
    if (valid) g_t[node] = tv;

    int lane = threadIdx.x & 31;
    unsigned ballot_valid = __ballot_sync(FULLMASK, valid);
    if (ballot_valid == 0) return;
    int nv = __popc(ballot_valid);

    int g0 = __shfl_sync(FULLMASK, g, 0);
    bool uniform = __all_sync(FULLMASK, (g == g0) || !valid);

    if (uniform) {
        float ss = valid ? s : 0.f;
        ss += __shfl_xor_sync(FULLMASK, ss, 1);
        ss += __shfl_xor_sync(FULLMASK, ss, 2);
        ss += __shfl_xor_sync(FULLMASK, ss, 4);
        ss += __shfl_xor_sync(FULLMASK, ss, 8);
        ss += __shfl_xor_sync(FULLMASK, ss, 16);
        if (lane == 0) {
            atomicAdd(&g_S[g0], ss + g_c * (float)nv);
            atomicAdd(&g_cnt[g0], (float)nv);
        }
    } else {
        if (valid) {
            atomicAdd(&g_S[g], s + g_c);
            atomicAdd(&g_cnt[g], 1.f);
        }
    }
}

// ---------------- K4: E[batch[dst]] += t[src]  (4 edges/thread, MLP=4) ----------
#define K4_EPT 4
__global__ void k4_edge_scalar(const int* __restrict__ edge_index,
                               const int* __restrict__ batch) {
    __shared__ float sE[NG];
    int t = threadIdx.x;
    if (t < NG) sE[t] = 0.f;
    __syncthreads();

    int base = blockIdx.x * blockDim.x * K4_EPT + t;
    int e0 = base;
    int e1 = base + blockDim.x;
    int e2 = base + blockDim.x * 2;
    int e3 = base + blockDim.x * 3;

    int s0 = 0, s1 = 0, s2 = 0, s3 = 0;
    int d0 = 0, d1 = 0, d2 = 0, d3 = 0;
    bool b0 = e0 < N_EDGES, b1 = e1 < N_EDGES, b2 = e2 < N_EDGES, b3 = e3 < N_EDGES;
    if (b0) { s0 = __ldg(edge_index + e0); d0 = __ldg(edge_index + N_EDGES + e0); }
    if (b1) { s1 = __ldg(edge_index + e1); d1 = __ldg(edge_index + N_EDGES + e1); }
    if (b2) { s2 = __ldg(edge_index + e2); d2 = __ldg(edge_index + N_EDGES + e2); }
    if (b3) { s3 = __ldg(edge_index + e3); d3 = __ldg(edge_index + N_EDGES + e3); }

    float t0 = 0.f, t1 = 0.f, t2 = 0.f, t3 = 0.f;
    int   gg0 = 0, gg1 = 0, gg2 = 0, gg3 = 0;
    if (b0) { t0 = __ldg(g_t + s0); gg0 = __ldg(batch + d0); }
    if (b1) { t1 = __ldg(g_t + s1); gg1 = __ldg(batch + d1); }
    if (b2) { t2 = __ldg(g_t + s2); gg2 = __ldg(batch + d2); }
    if (b3) { t3 = __ldg(g_t + s3); gg3 = __ldg(batch + d3); }

    if (b0) atomicAdd(&sE[gg0], t0);
    if (b1) atomicAdd(&sE[gg1], t1);
    if (b2) atomicAdd(&sE[gg2], t2);
    if (b3) atomicAdd(&sE[gg3], t3);

    __syncthreads();
    if (t < NG && sE[t] != 0.f) atomicAdd(&g_E[t], sE[t]);
}

// ---------------- K5: out[g] = (S+E)/max(cnt,1) + blin ---------------------------
__global__ void k5_final(const float* __restrict__ blin, float* __restrict__ out) {
    int g = threadIdx.x;
    if (g < NG) {
        float cnt = g_cnt[g];
        out[g] = (g_S[g] + g_E[g]) / fmaxf(cnt, 1.f) + blin[0];
    }
}

extern "C" void kernel_launch(void* const* d_in, const int* in_sizes, int n_in,
                              void* d_out, int out_size) {
    const float* x       = (const float*)d_in[0];
    const int*   eidx    = (const int*)d_in[1];    // int32 (JAX x64 disabled)
    const int*   batch   = (const int*)d_in[2];    // int32
    const float* W1_rel  = (const float*)d_in[3];
    const float* W1_root = (const float*)d_in[4];
    const float* b1      = (const float*)d_in[5];
    const float* W2_rel  = (const float*)d_in[6];
    const float* W2_root = (const float*)d_in[7];
    const float* b2      = (const float*)d_in[8];
    const float* Wlin    = (const float*)d_in[9];
    const float* blin    = (const float*)d_in[10];
    float* out = (float*)d_out;

    k0_setup<<<1, 128>>>(W2_rel, W2_root, b2, Wlin);

    {
        int total = N_NODES * NH;
        int tpb = 256;
        k1_node_proj<<<(total + tpb - 1) / tpb, tpb>>>(x, W1_rel, W1_root, b1);
    }
    {
        int tpb = 256;
        k2_edge_scatter<<<(N_EDGES + tpb - 1) / tpb, tpb>>>(eidx);
    }
    {
        int tpb = 128;
        k3_node_scalars<<<(N_NODES + tpb - 1) / tpb, tpb>>>(batch);
    }
    {
        int tpb = 256;
        int per_block = tpb * K4_EPT;
        k4_edge_scalar<<<(N_EDGES + per_block - 1) / per_block, tpb>>>(eidx, batch);
    }
    k5_final<<<1, 64>>>(blin, out);
}